// round 1
// baseline (speedup 1.0000x reference)
#include <cuda_runtime.h>

#define BB 64
#define SS 512
#define II 1024
#define HH 1024
#define NDELAY 4

typedef unsigned long long u64;
typedef unsigned int u32;

// ---------------- packed f32x2 helpers (FFMA2 path, PTX-only) ----------------
__device__ __forceinline__ u64 pack2(float lo, float hi) {
    u64 r; asm("mov.b64 %0, {%1, %2};" : "=l"(r) : "f"(lo), "f"(hi)); return r;
}
__device__ __forceinline__ u64 pack2dup(float v) {
    u64 r; asm("mov.b64 %0, {%1, %1};" : "=l"(r) : "f"(v)); return r;
}
__device__ __forceinline__ void fma2(u64 &d, u64 a, u64 b) {
    asm("fma.rn.f32x2 %0, %1, %2, %0;" : "+l"(d) : "l"(a), "l"(b));
}
__device__ __forceinline__ float2 unpack2(u64 v) {
    float2 f; asm("mov.b64 {%0, %1}, %2;" : "=f"(f.x), "=f"(f.y) : "l"(v)); return f;
}

// =============================================================================
// Phase 1: pre[b,s,n] = sum_i inputs[b,s,i]*Wih[n,i] + bih[n] + bhh[n]
// Written directly into the outs region of d_out (in-place pre-activations).
// Classic 128x128x8 tile, 256 threads, 8x8 per thread, f32x2 FMAs.
// M = B*S = 32768, N = 1024, K = 1024. Both operands K-contiguous (NT gemm).
// =============================================================================
__global__ __launch_bounds__(256)
void pre_gemm_kernel(const float* __restrict__ A, const float* __restrict__ W,
                     const float* __restrict__ bih, const float* __restrict__ bhh,
                     float* __restrict__ C)
{
    __shared__ float As[8][132];   // [k][m], padded stride 132 (16B-aligned rows, conflict-free stores)
    __shared__ float Ws[8][132];   // [k][n]
    const int tid  = threadIdx.x;
    const int bm   = blockIdx.y * 128;
    const int bn   = blockIdx.x * 128;
    const int lrow = tid >> 1;         // 0..127
    const int lcol = (tid & 1) << 2;   // 0 or 4
    const float* aptr = A + (size_t)(bm + lrow) * II + lcol;
    const float* wptr = W + (size_t)(bn + lrow) * II + lcol;
    const int ty = tid >> 4;           // 0..15
    const int tx = tid & 15;           // 0..15

    u64 acc[8][4];
#pragma unroll
    for (int i = 0; i < 8; i++)
#pragma unroll
        for (int j = 0; j < 4; j++) acc[i][j] = 0ull;

    float4 av = *(const float4*)aptr;
    float4 wv = *(const float4*)wptr;

    const int NT = II / 8;  // 128 k-tiles
    for (int t = 0; t < NT; t++) {
        As[lcol+0][lrow]=av.x; As[lcol+1][lrow]=av.y; As[lcol+2][lrow]=av.z; As[lcol+3][lrow]=av.w;
        Ws[lcol+0][lrow]=wv.x; Ws[lcol+1][lrow]=wv.y; Ws[lcol+2][lrow]=wv.z; Ws[lcol+3][lrow]=wv.w;
        __syncthreads();
        if (t + 1 < NT) {  // prefetch next tile into regs, overlap with compute
            av = *(const float4*)(aptr + (t+1)*8);
            wv = *(const float4*)(wptr + (t+1)*8);
        }
#pragma unroll
        for (int kk = 0; kk < 8; kk++) {
            float4 a0 = *(const float4*)&As[kk][ty*8];
            float4 a1 = *(const float4*)&As[kk][ty*8+4];
            float4 b0 = *(const float4*)&Ws[kk][tx*8];
            float4 b1 = *(const float4*)&Ws[kk][tx*8+4];
            u64 bp[4] = { pack2(b0.x,b0.y), pack2(b0.z,b0.w),
                          pack2(b1.x,b1.y), pack2(b1.z,b1.w) };
            float aa[8] = { a0.x,a0.y,a0.z,a0.w,a1.x,a1.y,a1.z,a1.w };
#pragma unroll
            for (int i = 0; i < 8; i++) {
                u64 ad = pack2dup(aa[i]);
                fma2(acc[i][0], ad, bp[0]);
                fma2(acc[i][1], ad, bp[1]);
                fma2(acc[i][2], ad, bp[2]);
                fma2(acc[i][3], ad, bp[3]);
            }
        }
        __syncthreads();
    }

#pragma unroll
    for (int i = 0; i < 8; i++) {
        const int m = bm + ty*8 + i;
        float* crow = C + (size_t)m * HH + bn + tx*8;
#pragma unroll
        for (int j = 0; j < 4; j++) {
            float2 v = unpack2(acc[i][j]);
            int n = bn + tx*8 + j*2;
            crow[j*2+0] = v.x + bih[n]   + bhh[n];
            crow[j*2+1] = v.y + bih[n+1] + bhh[n+1];
        }
    }
}

// =============================================================================
// Phase 2: recurrence. 128 sequential groups of 4 independent steps.
// Persistent kernel, grid = 128 blocks (16 n-tiles x 8 m-tiles), all co-resident
// (128 <= 148 SMs), software grid barrier between groups.
// Per group: C[256,64-tile] = Hprev[256,1024] @ Whh[64-tile,1024]^T,
// then out = tanh(pre + C) in place. Row r = d*64 + b.
// Barrier counters are monotonically increasing (replay-safe, zero-init).
// =============================================================================
__device__ u32 g_bar_slots[SS / NDELAY];

__device__ __forceinline__ void grid_barrier(u32* slot, u32 nb)
{
    __syncthreads();
    if (threadIdx.x == 0) {
        __threadfence();                       // release: my out-writes visible
        u32 v = atomicAdd(slot, 1u) + 1u;
        u32 target = ((v + nb - 1u) / nb) * nb;
        while (*(volatile u32*)slot < target) { }
        __threadfence();                       // acquire
    }
    __syncthreads();
}

__global__ __launch_bounds__(128)
void rnn_recurrent_kernel(const float* __restrict__ h0,
                          const float* __restrict__ W,
                          float* __restrict__ out)
{
    __shared__ float As[16][36];   // [k][m], 32 rows + pad
    __shared__ float Ws[16][68];   // [k][n], 64 cols + pad
    const int tid = threadIdx.x;
    const int nt  = blockIdx.x;    // 0..15 -> cols [64*nt, 64*nt+64)
    const int mt  = blockIdx.y;    // 0..7  -> rows [32*mt, 32*mt+32)
    const int d   = mt >> 1;       // delay-chain index, constant per m-tile
    const int ty  = tid >> 4;      // 0..7  -> thread rows ty*4..+3
    const int tx  = tid & 15;      // 0..15 -> thread cols tx*4..+3
    const int alr = tid >> 2;          // A-load row 0..31
    const int akc = (tid & 3) << 2;    // A-load k offset

    // Whh tile load mapping (same addresses every group -> L1-resident after g0)
    const int wn0 = tid >> 2;
    const int wn1 = 32 + (tid >> 2);
    const int wkc = (tid & 3) << 2;
    const float* wp0 = W + (size_t)(nt*64 + wn0) * HH + wkc;
    const float* wp1 = W + (size_t)(nt*64 + wn1) * HH + wkc;

    const u32 NB = gridDim.x * gridDim.y;   // 128
    const int NGROUP = SS / NDELAY;         // 128

    for (int g = 0; g < NGROUP; g++) {
        const float* abase;
        if (g == 0) {
            // hidden_state [4,64,1024] flattens exactly to row-major r = d*64+b
            abase = h0 + (size_t)(mt*32 + alr) * HH;
        } else {
            int b = ((mt & 1) << 5) + alr;
            int tprev = 4*(g-1) + d;
            abase = out + (size_t)(b*SS + tprev) * HH;
        }

        u64 acc[4][2];
#pragma unroll
        for (int i = 0; i < 4; i++) { acc[i][0] = 0ull; acc[i][1] = 0ull; }

        // __ldcg: A rows were written by other blocks last group; read from L2.
        float4 av  = __ldcg((const float4*)(abase + akc));
        float4 wv0 = *(const float4*)wp0;
        float4 wv1 = *(const float4*)wp1;

        const int NT = HH / 16;  // 64 k-tiles
        for (int t = 0; t < NT; t++) {
            As[akc+0][alr]=av.x;  As[akc+1][alr]=av.y;  As[akc+2][alr]=av.z;  As[akc+3][alr]=av.w;
            Ws[wkc+0][wn0]=wv0.x; Ws[wkc+1][wn0]=wv0.y; Ws[wkc+2][wn0]=wv0.z; Ws[wkc+3][wn0]=wv0.w;
            Ws[wkc+0][wn1]=wv1.x; Ws[wkc+1][wn1]=wv1.y; Ws[wkc+2][wn1]=wv1.z; Ws[wkc+3][wn1]=wv1.w;
            __syncthreads();
            if (t + 1 < NT) {
                int k0 = (t+1)*16;
                av  = __ldcg((const float4*)(abase + k0 + akc));
                wv0 = *(const float4*)(wp0 + k0);
                wv1 = *(const float4*)(wp1 + k0);
            }
#pragma unroll
            for (int kk = 0; kk < 16; kk++) {
                float4 a = *(const float4*)&As[kk][ty*4];
                float4 b = *(const float4*)&Ws[kk][tx*4];
                u64 bp0 = pack2(b.x, b.y);
                u64 bp1 = pack2(b.z, b.w);
                float aa[4] = { a.x, a.y, a.z, a.w };
#pragma unroll
                for (int i = 0; i < 4; i++) {
                    u64 ad = pack2dup(aa[i]);
                    fma2(acc[i][0], ad, bp0);
                    fma2(acc[i][1], ad, bp1);
                }
            }
            __syncthreads();
        }

        // epilogue: out = tanh(pre + acc), in place
        const int tcur = 4*g + d;
#pragma unroll
        for (int i = 0; i < 4; i++) {
            int lrow = ty*4 + i;
            int b = ((mt & 1) << 5) + lrow;
            float* crow = out + (size_t)(b*SS + tcur) * HH + nt*64 + tx*4;
            float2 v0 = unpack2(acc[i][0]);
            float2 v1 = unpack2(acc[i][1]);
            crow[0] = tanhf(crow[0] + v0.x);
            crow[1] = tanhf(crow[1] + v0.y);
            crow[2] = tanhf(crow[2] + v1.x);
            crow[3] = tanhf(crow[3] + v1.y);
        }

        if (g + 1 < NGROUP) grid_barrier(&g_bar_slots[g], NB);
    }
}

// =============================================================================
// Phase 3: h_final[d,b,h] = outs[b, S-4+d, h], appended after the outs region.
// =============================================================================
__global__ void copy_final_kernel(float* __restrict__ out)
{
    int idx = blockIdx.x * blockDim.x + threadIdx.x;
    const int total = NDELAY * BB * HH;   // 262144
    if (idx < total) {
        int h  = idx & (HH - 1);
        int b  = (idx >> 10) & (BB - 1);
        int dd = idx >> 16;
        out[(size_t)BB*SS*HH + idx] =
            out[(size_t)(b*SS + (SS - NDELAY + dd)) * HH + h];
    }
}

extern "C" void kernel_launch(void* const* d_in, const int* in_sizes, int n_in,
                              void* d_out, int out_size)
{
    const float* inputs = (const float*)d_in[0];   // [64,512,1024]
    const float* hidden = (const float*)d_in[1];   // [4,64,1024]
    const float* Wih    = (const float*)d_in[2];   // [1024,1024]
    const float* Whh    = (const float*)d_in[3];   // [1024,1024]
    const float* bih    = (const float*)d_in[4];   // [1024]
    const float* bhh    = (const float*)d_in[5];   // [1024]
    float* out = (float*)d_out;

    dim3 g1(HH/128, (BB*SS)/128);          // (8, 256)
    pre_gemm_kernel<<<g1, 256>>>(inputs, Wih, bih, bhh, out);

    dim3 g2(HH/64, (NDELAY*BB)/32);        // (16, 8) = 128 blocks, all co-resident
    rnn_recurrent_kernel<<<g2, 128>>>(hidden, Whh, out);

    copy_final_kernel<<<(NDELAY*BB*HH + 255)/256, 256>>>(out);
}

// round 3
// speedup vs baseline: 1.0032x; 1.0032x over previous
#include <cuda_runtime.h>

#define BB 64
#define SS 512
#define II 1024
#define HH 1024
#define NDELAY 4

typedef unsigned long long u64;
typedef unsigned int u32;

// ---------------- packed f32x2 helpers (FFMA2 path, PTX-only) ----------------
__device__ __forceinline__ u64 pack2(float lo, float hi) {
    u64 r; asm("mov.b64 %0, {%1, %2};" : "=l"(r) : "f"(lo), "f"(hi)); return r;
}
__device__ __forceinline__ u64 pack2dup(float v) {
    u64 r; asm("mov.b64 %0, {%1, %1};" : "=l"(r) : "f"(v)); return r;
}
__device__ __forceinline__ void fma2(u64 &d, u64 a, u64 b) {
    asm("fma.rn.f32x2 %0, %1, %2, %0;" : "+l"(d) : "l"(a), "l"(b));
}
__device__ __forceinline__ float2 unpack2(u64 v) {
    float2 f; asm("mov.b64 {%0, %1}, %2;" : "=f"(f.x), "=f"(f.y) : "l"(v)); return f;
}

// =============================================================================
// Phase 1: pre[b,s,n] = sum_i inputs[b,s,i]*Wih[n,i] + bih[n] + bhh[n]
// Written directly into the outs region of d_out (in-place pre-activations).
// Classic 128x128x8 tile, 256 threads, 8x8 per thread, f32x2 FMAs.
// M = B*S = 32768, N = 1024, K = 1024. Both operands K-contiguous (NT gemm).
// =============================================================================
__global__ __launch_bounds__(256)
void pre_gemm_kernel(const float* __restrict__ A, const float* __restrict__ W,
                     const float* __restrict__ bih, const float* __restrict__ bhh,
                     float* __restrict__ C)
{
    __shared__ float As[8][132];   // [k][m], padded stride 132 (16B-aligned rows, conflict-free stores)
    __shared__ float Ws[8][132];   // [k][n]
    const int tid  = threadIdx.x;
    const int bm   = blockIdx.y * 128;
    const int bn   = blockIdx.x * 128;
    const int lrow = tid >> 1;         // 0..127
    const int lcol = (tid & 1) << 2;   // 0 or 4
    const float* aptr = A + (size_t)(bm + lrow) * II + lcol;
    const float* wptr = W + (size_t)(bn + lrow) * II + lcol;
    const int ty = tid >> 4;           // 0..15
    const int tx = tid & 15;           // 0..15

    u64 acc[8][4];
#pragma unroll
    for (int i = 0; i < 8; i++)
#pragma unroll
        for (int j = 0; j < 4; j++) acc[i][j] = 0ull;

    float4 av = *(const float4*)aptr;
    float4 wv = *(const float4*)wptr;

    const int NT = II / 8;  // 128 k-tiles
    for (int t = 0; t < NT; t++) {
        As[lcol+0][lrow]=av.x; As[lcol+1][lrow]=av.y; As[lcol+2][lrow]=av.z; As[lcol+3][lrow]=av.w;
        Ws[lcol+0][lrow]=wv.x; Ws[lcol+1][lrow]=wv.y; Ws[lcol+2][lrow]=wv.z; Ws[lcol+3][lrow]=wv.w;
        __syncthreads();
        if (t + 1 < NT) {  // prefetch next tile into regs, overlap with compute
            av = *(const float4*)(aptr + (t+1)*8);
            wv = *(const float4*)(wptr + (t+1)*8);
        }
#pragma unroll
        for (int kk = 0; kk < 8; kk++) {
            float4 a0 = *(const float4*)&As[kk][ty*8];
            float4 a1 = *(const float4*)&As[kk][ty*8+4];
            float4 b0 = *(const float4*)&Ws[kk][tx*8];
            float4 b1 = *(const float4*)&Ws[kk][tx*8+4];
            u64 bp[4] = { pack2(b0.x,b0.y), pack2(b0.z,b0.w),
                          pack2(b1.x,b1.y), pack2(b1.z,b1.w) };
            float aa[8] = { a0.x,a0.y,a0.z,a0.w,a1.x,a1.y,a1.z,a1.w };
#pragma unroll
            for (int i = 0; i < 8; i++) {
                u64 ad = pack2dup(aa[i]);
                fma2(acc[i][0], ad, bp[0]);
                fma2(acc[i][1], ad, bp[1]);
                fma2(acc[i][2], ad, bp[2]);
                fma2(acc[i][3], ad, bp[3]);
            }
        }
        __syncthreads();
    }

#pragma unroll
    for (int i = 0; i < 8; i++) {
        const int m = bm + ty*8 + i;
        float* crow = C + (size_t)m * HH + bn + tx*8;
#pragma unroll
        for (int j = 0; j < 4; j++) {
            float2 v = unpack2(acc[i][j]);
            int n = bn + tx*8 + j*2;
            crow[j*2+0] = v.x + bih[n]   + bhh[n];
            crow[j*2+1] = v.y + bih[n+1] + bhh[n+1];
        }
    }
}

// =============================================================================
// Phase 2: recurrence. 128 sequential groups of 4 independent steps.
// Persistent kernel, grid = 128 blocks (16 n-tiles x 8 m-tiles), all co-resident
// (128 <= 148 SMs), software grid barrier between groups.
// Per group: C[256,64-tile] = Hprev[256,1024] @ Whh[64-tile,1024]^T,
// then out = tanh(pre + C) in place. Row r = d*64 + b.
// Barrier counters are monotonically increasing (replay-safe, zero-init).
// =============================================================================
__device__ u32 g_bar_slots[SS / NDELAY];

__device__ __forceinline__ void grid_barrier(u32* slot, u32 nb)
{
    __syncthreads();
    if (threadIdx.x == 0) {
        __threadfence();                       // release: my out-writes visible
        u32 v = atomicAdd(slot, 1u) + 1u;
        u32 target = ((v + nb - 1u) / nb) * nb;
        while (*(volatile u32*)slot < target) { }
        __threadfence();                       // acquire
    }
    __syncthreads();
}

__global__ __launch_bounds__(128)
void rnn_recurrent_kernel(const float* __restrict__ h0,
                          const float* __restrict__ W,
                          float* __restrict__ out)
{
    __shared__ float As[16][36];   // [k][m], 32 rows + pad
    __shared__ float Ws[16][68];   // [k][n], 64 cols + pad
    const int tid = threadIdx.x;
    const int nt  = blockIdx.x;    // 0..15 -> cols [64*nt, 64*nt+64)
    const int mt  = blockIdx.y;    // 0..7  -> rows [32*mt, 32*mt+32)
    const int d   = mt >> 1;       // delay-chain index, constant per m-tile
    const int ty  = tid >> 4;      // 0..7  -> thread rows ty*4..+3
    const int tx  = tid & 15;      // 0..15 -> thread cols tx*4..+3
    const int alr = tid >> 2;          // A-load row 0..31
    const int akc = (tid & 3) << 2;    // A-load k offset

    // Whh tile load mapping (same addresses every group -> L1-resident after g0)
    const int wn0 = tid >> 2;
    const int wn1 = 32 + (tid >> 2);
    const int wkc = (tid & 3) << 2;
    const float* wp0 = W + (size_t)(nt*64 + wn0) * HH + wkc;
    const float* wp1 = W + (size_t)(nt*64 + wn1) * HH + wkc;

    const u32 NB = gridDim.x * gridDim.y;   // 128
    const int NGROUP = SS / NDELAY;         // 128

    for (int g = 0; g < NGROUP; g++) {
        const float* abase;
        if (g == 0) {
            // hidden_state [4,64,1024] flattens exactly to row-major r = d*64+b
            abase = h0 + (size_t)(mt*32 + alr) * HH;
        } else {
            int b = ((mt & 1) << 5) + alr;
            int tprev = 4*(g-1) + d;
            abase = out + (size_t)(b*SS + tprev) * HH;
        }

        u64 acc[4][2];
#pragma unroll
        for (int i = 0; i < 4; i++) { acc[i][0] = 0ull; acc[i][1] = 0ull; }

        // __ldcg: A rows were written by other blocks last group; read from L2.
        float4 av  = __ldcg((const float4*)(abase + akc));
        float4 wv0 = *(const float4*)wp0;
        float4 wv1 = *(const float4*)wp1;

        const int NT = HH / 16;  // 64 k-tiles
        for (int t = 0; t < NT; t++) {
            As[akc+0][alr]=av.x;  As[akc+1][alr]=av.y;  As[akc+2][alr]=av.z;  As[akc+3][alr]=av.w;
            Ws[wkc+0][wn0]=wv0.x; Ws[wkc+1][wn0]=wv0.y; Ws[wkc+2][wn0]=wv0.z; Ws[wkc+3][wn0]=wv0.w;
            Ws[wkc+0][wn1]=wv1.x; Ws[wkc+1][wn1]=wv1.y; Ws[wkc+2][wn1]=wv1.z; Ws[wkc+3][wn1]=wv1.w;
            __syncthreads();
            if (t + 1 < NT) {
                int k0 = (t+1)*16;
                av  = __ldcg((const float4*)(abase + k0 + akc));
                wv0 = *(const float4*)(wp0 + k0);
                wv1 = *(const float4*)(wp1 + k0);
            }
#pragma unroll
            for (int kk = 0; kk < 16; kk++) {
                float4 a = *(const float4*)&As[kk][ty*4];
                float4 b = *(const float4*)&Ws[kk][tx*4];
                u64 bp0 = pack2(b.x, b.y);
                u64 bp1 = pack2(b.z, b.w);
                float aa[4] = { a.x, a.y, a.z, a.w };
#pragma unroll
                for (int i = 0; i < 4; i++) {
                    u64 ad = pack2dup(aa[i]);
                    fma2(acc[i][0], ad, bp0);
                    fma2(acc[i][1], ad, bp1);
                }
            }
            __syncthreads();
        }

        // epilogue: out = tanh(pre + acc), in place
        const int tcur = 4*g + d;
#pragma unroll
        for (int i = 0; i < 4; i++) {
            int lrow = ty*4 + i;
            int b = ((mt & 1) << 5) + lrow;
            float* crow = out + (size_t)(b*SS + tcur) * HH + nt*64 + tx*4;
            float2 v0 = unpack2(acc[i][0]);
            float2 v1 = unpack2(acc[i][1]);
            crow[0] = tanhf(crow[0] + v0.x);
            crow[1] = tanhf(crow[1] + v0.y);
            crow[2] = tanhf(crow[2] + v1.x);
            crow[3] = tanhf(crow[3] + v1.y);
        }

        if (g + 1 < NGROUP) grid_barrier(&g_bar_slots[g], NB);
    }
}

// =============================================================================
// Phase 3: h_final[d,b,h] = outs[b, S-4+d, h], appended after the outs region.
// =============================================================================
__global__ void copy_final_kernel(float* __restrict__ out)
{
    int idx = blockIdx.x * blockDim.x + threadIdx.x;
    const int total = NDELAY * BB * HH;   // 262144
    if (idx < total) {
        int h  = idx & (HH - 1);
        int b  = (idx >> 10) & (BB - 1);
        int dd = idx >> 16;
        out[(size_t)BB*SS*HH + idx] =
            out[(size_t)(b*SS + (SS - NDELAY + dd)) * HH + h];
    }
}

extern "C" void kernel_launch(void* const* d_in, const int* in_sizes, int n_in,
                              void* d_out, int out_size)
{
    const float* inputs = (const float*)d_in[0];   // [64,512,1024]
    const float* hidden = (const float*)d_in[1];   // [4,64,1024]
    const float* Wih    = (const float*)d_in[2];   // [1024,1024]
    const float* Whh    = (const float*)d_in[3];   // [1024,1024]
    const float* bih    = (const float*)d_in[4];   // [1024]
    const float* bhh    = (const float*)d_in[5];   // [1024]
    float* out = (float*)d_out;

    dim3 g1(HH/128, (BB*SS)/128);          // (8, 256)
    pre_gemm_kernel<<<g1, 256>>>(inputs, Wih, bih, bhh, out);

    dim3 g2(HH/64, (NDELAY*BB)/32);        // (16, 8) = 128 blocks, all co-resident
    rnn_recurrent_kernel<<<g2, 128>>>(hidden, Whh, out);

    copy_final_kernel<<<(NDELAY*BB*HH + 255)/256, 256>>>(out);
}

// round 9
// speedup vs baseline: 1.9734x; 1.9670x over previous
#include <cuda_runtime.h>
#include <cuda_bf16.h>
#include <cstdint>

#define BB 64
#define SSL 512
#define II 1024
#define HH 1024
#define RING (256*1024)

typedef unsigned int u32;
typedef unsigned long long u64;

// ---------------- persistent device scratch ----------------
__device__ __align__(256) __nv_bfloat16 g_Ahi[(size_t)BB*SSL*II];
__device__ __align__(256) __nv_bfloat16 g_Alo[(size_t)BB*SSL*II];
__device__ __align__(256) __nv_bfloat16 g_Wihh[II*HH];
__device__ __align__(256) __nv_bfloat16 g_Wihl[II*HH];
__device__ __align__(256) __nv_bfloat16 g_Whhh[HH*HH];
__device__ __align__(256) __nv_bfloat16 g_Whhl[HH*HH];
__device__ __align__(256) __nv_bfloat16 g_rh[2*RING];
__device__ __align__(256) __nv_bfloat16 g_rl[2*RING];
__device__ u32 g_bars[256];

// ---------------- helpers ----------------
__device__ __forceinline__ u32 smem_u32(const void* p) {
    u32 a; asm("{ .reg .u64 t; cvta.to.shared.u64 t, %1; cvt.u32.u64 %0, t; }" : "=r"(a) : "l"(p));
    return a;
}
__device__ __forceinline__ u32 pack_bf16x2(float a, float b) {
    u32 r; asm("cvt.rn.bf16x2.f32 %0, %1, %2;" : "=r"(r) : "f"(b), "f"(a));
    return r;
}
__device__ __forceinline__ float bf16_hi_f32(float x) {
    u32 r; asm("cvt.rn.bf16x2.f32 %0, %1, %2;" : "=r"(r) : "f"(0.0f), "f"(x));
    return __uint_as_float(r << 16);
}
__device__ __forceinline__ float fast_tanh(float x) {
    float a = fabsf(x);
    float e = __expf(-2.0f * a);
    float r = __fdividef(1.0f - e, 1.0f + e);
    return copysignf(r, x);
}
#define CP16(smem_addr, gptr) \
    asm volatile("cp.async.cg.shared.global [%0], [%1], 16;" :: "r"(smem_addr), "l"(gptr))
#define CP_COMMIT() asm volatile("cp.async.commit_group;" ::: "memory")
#define CP_WAIT(n)  asm volatile("cp.async.wait_group %0;" :: "n"(n) : "memory")

__device__ __forceinline__ void ldmx4(u32* r, u32 addr) {
    asm volatile("ldmatrix.sync.aligned.m8n8.x4.shared.b16 {%0,%1,%2,%3}, [%4];"
        : "=r"(r[0]), "=r"(r[1]), "=r"(r[2]), "=r"(r[3]) : "r"(addr));
}
__device__ __forceinline__ void mma16816(float* c, const u32* a, const u32* b) {
    asm volatile("mma.sync.aligned.m16n8k16.row.col.f32.bf16.bf16.f32 "
        "{%0,%1,%2,%3}, {%4,%5,%6,%7}, {%8,%9}, {%0,%1,%2,%3};"
        : "+f"(c[0]), "+f"(c[1]), "+f"(c[2]), "+f"(c[3])
        : "r"(a[0]), "r"(a[1]), "r"(a[2]), "r"(a[3]), "r"(b[0]), "r"(b[1]));
}

// ============================================================================
// fp32 -> bf16 hi/lo split. which: 0=inputs, 1=Wih, 2=Whh, 3=h0->ring slot0
// ============================================================================
__global__ void split_kernel(const float* __restrict__ src, int which, int n4)
{
    int i = blockIdx.x * blockDim.x + threadIdx.x;
    if (i >= n4) return;
    __nv_bfloat16 *hi, *lo;
    if      (which == 0) { hi = g_Ahi;  lo = g_Alo;  }
    else if (which == 1) { hi = g_Wihh; lo = g_Wihl; }
    else if (which == 2) { hi = g_Whhh; lo = g_Whhl; }
    else                 { hi = g_rh;   lo = g_rl;   }
    float4 v = ((const float4*)src)[i];
    float h0 = bf16_hi_f32(v.x), h1 = bf16_hi_f32(v.y);
    float h2 = bf16_hi_f32(v.z), h3 = bf16_hi_f32(v.w);
    ((u32*)hi)[2*i+0] = pack_bf16x2(v.x, v.y);
    ((u32*)hi)[2*i+1] = pack_bf16x2(v.z, v.w);
    ((u32*)lo)[2*i+0] = pack_bf16x2(v.x - h0, v.y - h1);
    ((u32*)lo)[2*i+1] = pack_bf16x2(v.z - h2, v.w - h3);
}

// ============================================================================
// Phase 1: pre = inputs @ Wih^T + bih + bhh   (mma.sync bf16, 3-product split)
// 128x128 tile, KC=64, cp.async double buffer, 256 thr, warp tile 64x32.
// ============================================================================
#define P1_AST 72
#define P1_TILE (128*P1_AST*2)     // 18432 B
#define P1_BUF  (4*P1_TILE)        // Ah Al Bh Bl
#define P1_BYTES (2*P1_BUF)        // 147456 B

__global__ __launch_bounds__(256, 1)
void gemm1_kernel(const float* __restrict__ bih, const float* __restrict__ bhh,
                  float* __restrict__ out)
{
    extern __shared__ char smem[];
    const u32 sb = smem_u32(smem);
    const int tid = threadIdx.x, wid = tid >> 5, lane = tid & 31;
    const int bm = blockIdx.y * 128, bn = blockIdx.x * 128;
    const int m_base = (wid >> 2) * 64;     // 0 or 64
    const int n_base = (wid & 3) * 32;      // 0,32,64,96

    auto load_chunk = [&](int s, int buf) {
        const int k0 = s * 64;
        const u32 base = sb + buf * P1_BUF;
#pragma unroll
        for (int it = 0; it < 4; it++) {
            int v = tid + it * 256;        // 0..1023
            int r = v >> 3, c = (v & 7) * 8;
            u32 so = (u32)(r * P1_AST + c) * 2;
            size_t gA = (size_t)(bm + r) * II + k0 + c;
            size_t gW = (size_t)(bn + r) * II + k0 + c;
            CP16(base + so,               g_Ahi + gA);
            CP16(base + P1_TILE + so,     g_Alo + gA);
            CP16(base + 2*P1_TILE + so,   g_Wihh + gW);
            CP16(base + 3*P1_TILE + so,   g_Wihl + gW);
        }
    };

    float acc[4][4][4];
#pragma unroll
    for (int i = 0; i < 4; i++)
#pragma unroll
        for (int j = 0; j < 4; j++)
#pragma unroll
            for (int q = 0; q < 4; q++) acc[i][j][q] = 0.0f;

    load_chunk(0, 0); CP_COMMIT();
    for (int s = 0; s < 16; s++) {
        const int b = s & 1;
        if (s + 1 < 16) load_chunk(s + 1, b ^ 1);
        CP_COMMIT();
        CP_WAIT(1);
        __syncthreads();
        const u32 abase = sb + b * P1_BUF;
        const u32 bbase = abase + 2 * P1_TILE;
#pragma unroll
        for (int ks = 0; ks < 4; ks++) {
            const int k16 = ks * 16;
            const u32 acol = (u32)(k16 + ((lane >> 4) << 3));
            const u32 arow = (u32)(m_base + (lane & 15));
            const u32 brow = (u32)(n_base + (lane & 7) + ((lane & 16) >> 1));
            const u32 bcol = (u32)(k16 + (lane & 8));
            u32 af[4][4], bh[8], bl[8];
#pragma unroll
            for (int j = 0; j < 2; j++) {
                u32 bd = bbase + ((brow + j*16) * P1_AST + bcol) * 2;
                ldmx4(&bh[j*4], bd);
                ldmx4(&bl[j*4], bd + P1_TILE);
            }
#pragma unroll
            for (int im = 0; im < 4; im++)
                ldmx4(af[im], abase + ((arow + im*16) * P1_AST + acol) * 2);   // Ah
#pragma unroll
            for (int im = 0; im < 4; im++)
#pragma unroll
                for (int jn = 0; jn < 4; jn++) {
                    mma16816(acc[im][jn], af[im], &bh[jn*2]);   // Ah*Bh
                    mma16816(acc[im][jn], af[im], &bl[jn*2]);   // Ah*Bl
                }
#pragma unroll
            for (int im = 0; im < 4; im++)
                ldmx4(af[im], abase + P1_TILE + ((arow + im*16) * P1_AST + acol) * 2);  // Al
#pragma unroll
            for (int im = 0; im < 4; im++)
#pragma unroll
                for (int jn = 0; jn < 4; jn++)
                    mma16816(acc[im][jn], af[im], &bh[jn*2]);   // Al*Bh
        }
        __syncthreads();
    }

    // epilogue: add biases, store fp32
#pragma unroll
    for (int im = 0; im < 4; im++) {
        int r0 = bm + m_base + im*16 + (lane >> 2);
#pragma unroll
        for (int jn = 0; jn < 4; jn++) {
            int n = bn + n_base + jn*8 + (lane & 3) * 2;
            float2 b1 = *(const float2*)(bih + n);
            float2 b2 = *(const float2*)(bhh + n);
            float bx = b1.x + b2.x, by = b1.y + b2.y;
            float2 v0 = make_float2(acc[im][jn][0] + bx, acc[im][jn][1] + by);
            float2 v1 = make_float2(acc[im][jn][2] + bx, acc[im][jn][3] + by);
            *(float2*)(out + (size_t)r0 * HH + n)       = v0;
            *(float2*)(out + (size_t)(r0+8) * HH + n)   = v1;
        }
    }
}

// ============================================================================
// Phase 2: recurrence. 128 persistent blocks (4 mt x 64 rows, 32 nt x 32 cols),
// Whh slice persistent in SMEM, A (hidden ring) cp.async pipelined, 128 groups,
// one grid barrier per group. 128 threads, warp tile 32x16 (warps 2m x 2n).
// ============================================================================
#define P2_AST 72
#define P2_ATILE (64*P2_AST*2)     // 9216
#define P2_ABUF  (2*P2_ATILE)      // 18432
#define P2_BST 1032
#define P2_BTILE (32*P2_BST*2)     // 66048
#define P2_BYTES (2*P2_BTILE + 2*P2_ABUF)   // 168960

__global__ __launch_bounds__(128, 1)
void rnn2_kernel(float* __restrict__ out)
{
    extern __shared__ char smem[];
    const u32 sb  = smem_u32(smem);
    const u32 sbB = sb;                     // Bh, then Bl at +P2_BTILE
    const u32 sbA = sb + 2 * P2_BTILE;
    const int tid = threadIdx.x, wid = tid >> 5, lane = tid & 31;
    const int mt  = blockIdx.x >> 5;        // 0..3  -> rows mt*64
    const int ntc = blockIdx.x & 31;        // 0..31 -> cols ntc*32
    const int wm = wid >> 1, wn = wid & 1;  // warp tile 32m x 16n
    const u32 NB = 128;

    // ---- load persistent Whh slice (32 n-rows x 1024 k), hi+lo ----
#pragma unroll
    for (int it = 0; it < 32; it++) {
        int v = tid + it * 128;             // 0..4095
        int r = v >> 7, c = (v & 127) * 8;
        u32 so = (u32)(r * P2_BST + c) * 2;
        size_t gw = (size_t)(ntc*32 + r) * HH + c;
        CP16(sbB + so,            g_Whhh + gw);
        CP16(sbB + P2_BTILE + so, g_Whhl + gw);
    }
    CP_COMMIT(); CP_WAIT(0);
    __syncthreads();

    for (int g = 0; g < 128; g++) {
        const int rslot = g & 1, wslot = rslot ^ 1;
        const __nv_bfloat16* Ah = g_rh + (size_t)rslot * RING;
        const __nv_bfloat16* Al = g_rl + (size_t)rslot * RING;

        auto load_a = [&](int s, int buf) {
            const int k0 = s * 64;
            const u32 base = sbA + buf * P2_ABUF;
#pragma unroll
            for (int it = 0; it < 4; it++) {
                int v = tid + it * 128;     // 0..511
                int r = v >> 3, c = (v & 7) * 8;
                u32 so = (u32)(r * P2_AST + c) * 2;
                size_t ga = (size_t)(mt*64 + r) * HH + k0 + c;
                CP16(base + so,             Ah + ga);
                CP16(base + P2_ATILE + so,  Al + ga);
            }
        };

        float acc[2][2][4];
#pragma unroll
        for (int i = 0; i < 2; i++)
#pragma unroll
            for (int j = 0; j < 2; j++)
#pragma unroll
                for (int q = 0; q < 4; q++) acc[i][j][q] = 0.0f;

        load_a(0, 0); CP_COMMIT();
        for (int s = 0; s < 16; s++) {
            const int b = s & 1;
            if (s + 1 < 16) load_a(s + 1, b ^ 1);
            CP_COMMIT();
            CP_WAIT(1);
            __syncthreads();
            const u32 abase = sbA + b * P2_ABUF;
#pragma unroll
            for (int ks = 0; ks < 4; ks++) {
                const int k16a = ks * 16;
                const int k16g = s * 64 + k16a;
                const u32 arow = (u32)(wm*32 + (lane & 15));
                const u32 acol = (u32)(k16a + ((lane >> 4) << 3));
                const u32 brow = (u32)(wn*16 + (lane & 7) + ((lane & 16) >> 1));
                const u32 bcol = (u32)(k16g + (lane & 8));
                u32 ah[2][4], al[2][4], bh[4], bl[4];
                u32 bd = sbB + (brow * P2_BST + bcol) * 2;
                ldmx4(bh, bd);
                ldmx4(bl, bd + P2_BTILE);
#pragma unroll
                for (int im = 0; im < 2; im++) {
                    u32 ad = abase + ((arow + im*16) * P2_AST + acol) * 2;
                    ldmx4(ah[im], ad);
                    ldmx4(al[im], ad + P2_ATILE);
                }
#pragma unroll
                for (int im = 0; im < 2; im++)
#pragma unroll
                    for (int jn = 0; jn < 2; jn++) {
                        mma16816(acc[im][jn], ah[im], &bh[jn*2]);
                        mma16816(acc[im][jn], ah[im], &bl[jn*2]);
                        mma16816(acc[im][jn], al[im], &bh[jn*2]);
                    }
            }
            __syncthreads();
        }

        // ---- epilogue: tanh(pre + acc) -> out (fp32) + hidden ring (bf16 hi/lo)
#pragma unroll
        for (int im = 0; im < 2; im++) {
            int rA = mt*64 + wm*32 + im*16 + (lane >> 2);
#pragma unroll
            for (int jn = 0; jn < 2; jn++) {
                int n = ntc*32 + wn*16 + jn*8 + (lane & 3) * 2;
#pragma unroll
                for (int half = 0; half < 2; half++) {
                    int r = rA + half * 8;
                    float v0 = acc[im][jn][half*2], v1 = acc[im][jn][half*2+1];
                    int d = r >> 6, bidx = r & 63, t = 4*g + d;
                    float* prow = out + ((size_t)bidx * SSL + t) * HH + n;
                    float2 p = *(float2*)prow;
                    float h0 = fast_tanh(p.x + v0);
                    float h1 = fast_tanh(p.y + v1);
                    *(float2*)prow = make_float2(h0, h1);
                    float q0 = bf16_hi_f32(h0), q1 = bf16_hi_f32(h1);
                    size_t rb = (size_t)wslot * RING + (size_t)r * HH + n;
                    *(u32*)(g_rh + rb) = pack_bf16x2(h0, h1);
                    *(u32*)(g_rl + rb) = pack_bf16x2(h0 - q0, h1 - q1);
                }
            }
        }

        // ---- grid barrier ----
        if (g + 1 < 128) {
            __threadfence();
            __syncthreads();
            if (tid == 0) {
                u32 v = atomicAdd(&g_bars[g], 1u) + 1u;
                u32 target = ((v + NB - 1u) / NB) * NB;
                while (*(volatile u32*)&g_bars[g] < target) { }
            }
            __syncthreads();
        }
    }
}

// ============================================================================
// Phase 3: h_final[d,b,h] = outs[b, S-4+d, h]
// ============================================================================
__global__ void copy_final_kernel(float* __restrict__ out)
{
    int idx = blockIdx.x * blockDim.x + threadIdx.x;
    const int total = 4 * BB * HH;
    if (idx < total) {
        int h  = idx & (HH - 1);
        int b  = (idx >> 10) & (BB - 1);
        int dd = idx >> 16;
        out[(size_t)BB*SSL*HH + idx] =
            out[(size_t)(b*SSL + (SSL - 4 + dd)) * HH + h];
    }
}

extern "C" void kernel_launch(void* const* d_in, const int* in_sizes, int n_in,
                              void* d_out, int out_size)
{
    const float* inputs = (const float*)d_in[0];
    const float* hidden = (const float*)d_in[1];
    const float* Wih    = (const float*)d_in[2];
    const float* Whh    = (const float*)d_in[3];
    const float* bih    = (const float*)d_in[4];
    const float* bhh    = (const float*)d_in[5];
    float* out = (float*)d_out;

    cudaFuncSetAttribute(gemm1_kernel, cudaFuncAttributeMaxDynamicSharedMemorySize, P1_BYTES);
    cudaFuncSetAttribute(rnn2_kernel,  cudaFuncAttributeMaxDynamicSharedMemorySize, P2_BYTES);

    split_kernel<<<(BB*SSL*II/4 + 255)/256, 256>>>(inputs, 0, BB*SSL*II/4);
    split_kernel<<<(II*HH/4 + 255)/256, 256>>>(Wih, 1, II*HH/4);
    split_kernel<<<(HH*HH/4 + 255)/256, 256>>>(Whh, 2, HH*HH/4);
    split_kernel<<<(4*BB*HH/4 + 255)/256, 256>>>(hidden, 3, 4*BB*HH/4);

    dim3 g1(HH/128, (BB*SSL)/128);     // (8, 256) = 2048 blocks
    gemm1_kernel<<<g1, 256, P1_BYTES>>>(bih, bhh, out);

    rnn2_kernel<<<128, 128, P2_BYTES>>>(out);

    copy_final_kernel<<<(4*BB*HH + 255)/256, 256>>>(out);
}

// round 11
// speedup vs baseline: 2.1830x; 1.1062x over previous
#include <cuda_runtime.h>
#include <cuda_bf16.h>
#include <cstdint>

#define BB 64
#define SSL 512
#define II 1024
#define HH 1024
#define RING (256*1024)

typedef unsigned int u32;
typedef unsigned long long u64;

// ---------------- persistent device scratch ----------------
__device__ __align__(256) __nv_bfloat16 g_Ahi[(size_t)BB*SSL*II];
__device__ __align__(256) __nv_bfloat16 g_Alo[(size_t)BB*SSL*II];
__device__ __align__(256) __nv_bfloat16 g_Wihh[II*HH];
__device__ __align__(256) __nv_bfloat16 g_Wihl[II*HH];
__device__ __align__(256) __nv_bfloat16 g_Whhh[HH*HH];
__device__ __align__(256) __nv_bfloat16 g_Whhl[HH*HH];
__device__ __align__(256) __nv_bfloat16 g_rh[2*RING];
__device__ __align__(256) __nv_bfloat16 g_rl[2*RING];
__device__ u32 g_bars[256];

// ---------------- helpers ----------------
__device__ __forceinline__ u32 smem_u32(const void* p) {
    u32 a; asm("{ .reg .u64 t; cvta.to.shared.u64 t, %1; cvt.u32.u64 %0, t; }" : "=r"(a) : "l"(p));
    return a;
}
__device__ __forceinline__ u32 pack_bf16x2(float a, float b) {
    u32 r; asm("cvt.rn.bf16x2.f32 %0, %1, %2;" : "=r"(r) : "f"(b), "f"(a));
    return r;
}
__device__ __forceinline__ float bf16_hi_f32(float x) {
    u32 r; asm("cvt.rn.bf16x2.f32 %0, %1, %2;" : "=r"(r) : "f"(0.0f), "f"(x));
    return __uint_as_float(r << 16);
}
__device__ __forceinline__ float fast_tanh(float x) {
    float a = fabsf(x);
    float e = __expf(-2.0f * a);
    float r = __fdividef(1.0f - e, 1.0f + e);
    return copysignf(r, x);
}
#define CP16(smem_addr, gptr) \
    asm volatile("cp.async.cg.shared.global [%0], [%1], 16;" :: "r"(smem_addr), "l"(gptr))
#define CP_COMMIT() asm volatile("cp.async.commit_group;" ::: "memory")
#define CP_WAIT(n)  asm volatile("cp.async.wait_group %0;" :: "n"(n) : "memory")

__device__ __forceinline__ void ldmx4(u32* r, u32 addr) {
    asm volatile("ldmatrix.sync.aligned.m8n8.x4.shared.b16 {%0,%1,%2,%3}, [%4];"
        : "=r"(r[0]), "=r"(r[1]), "=r"(r[2]), "=r"(r[3]) : "r"(addr));
}
__device__ __forceinline__ void mma16816(float* c, const u32* a, const u32* b) {
    asm volatile("mma.sync.aligned.m16n8k16.row.col.f32.bf16.bf16.f32 "
        "{%0,%1,%2,%3}, {%4,%5,%6,%7}, {%8,%9}, {%0,%1,%2,%3};"
        : "+f"(c[0]), "+f"(c[1]), "+f"(c[2]), "+f"(c[3])
        : "r"(a[0]), "r"(a[1]), "r"(a[2]), "r"(a[3]), "r"(b[0]), "r"(b[1]));
}

// ============================================================================
// fp32 -> bf16 hi/lo split. which: 0=inputs, 1=Wih, 2=Whh, 3=h0->ring slot0
// ============================================================================
__global__ void split_kernel(const float* __restrict__ src, int which, int n4)
{
    int i = blockIdx.x * blockDim.x + threadIdx.x;
    if (i >= n4) return;
    __nv_bfloat16 *hi, *lo;
    if      (which == 0) { hi = g_Ahi;  lo = g_Alo;  }
    else if (which == 1) { hi = g_Wihh; lo = g_Wihl; }
    else if (which == 2) { hi = g_Whhh; lo = g_Whhl; }
    else                 { hi = g_rh;   lo = g_rl;   }
    float4 v = ((const float4*)src)[i];
    float h0 = bf16_hi_f32(v.x), h1 = bf16_hi_f32(v.y);
    float h2 = bf16_hi_f32(v.z), h3 = bf16_hi_f32(v.w);
    ((u32*)hi)[2*i+0] = pack_bf16x2(v.x, v.y);
    ((u32*)hi)[2*i+1] = pack_bf16x2(v.z, v.w);
    ((u32*)lo)[2*i+0] = pack_bf16x2(v.x - h0, v.y - h1);
    ((u32*)lo)[2*i+1] = pack_bf16x2(v.z - h2, v.w - h3);
}

// ============================================================================
// Phase 1: pre = inputs @ Wih^T + bih + bhh   (mma.sync bf16, 3-product split)
// 128x128 tile, KC=64, cp.async double buffer, 256 thr, warp tile 64x32.
// ============================================================================
#define P1_AST 72
#define P1_TILE (128*P1_AST*2)     // 18432 B
#define P1_BUF  (4*P1_TILE)        // Ah Al Bh Bl
#define P1_BYTES (2*P1_BUF)        // 147456 B

__global__ __launch_bounds__(256, 1)
void gemm1_kernel(const float* __restrict__ bih, const float* __restrict__ bhh,
                  float* __restrict__ out)
{
    extern __shared__ char smem[];
    const u32 sb = smem_u32(smem);
    const int tid = threadIdx.x, wid = tid >> 5, lane = tid & 31;
    const int bm = blockIdx.y * 128, bn = blockIdx.x * 128;
    const int m_base = (wid >> 2) * 64;     // 0 or 64
    const int n_base = (wid & 3) * 32;      // 0,32,64,96

    auto load_chunk = [&](int s, int buf) {
        const int k0 = s * 64;
        const u32 base = sb + buf * P1_BUF;
#pragma unroll
        for (int it = 0; it < 4; it++) {
            int v = tid + it * 256;        // 0..1023
            int r = v >> 3, c = (v & 7) * 8;
            u32 so = (u32)(r * P1_AST + c) * 2;
            size_t gA = (size_t)(bm + r) * II + k0 + c;
            size_t gW = (size_t)(bn + r) * II + k0 + c;
            CP16(base + so,               g_Ahi + gA);
            CP16(base + P1_TILE + so,     g_Alo + gA);
            CP16(base + 2*P1_TILE + so,   g_Wihh + gW);
            CP16(base + 3*P1_TILE + so,   g_Wihl + gW);
        }
    };

    float acc[4][4][4];
#pragma unroll
    for (int i = 0; i < 4; i++)
#pragma unroll
        for (int j = 0; j < 4; j++)
#pragma unroll
            for (int q = 0; q < 4; q++) acc[i][j][q] = 0.0f;

    load_chunk(0, 0); CP_COMMIT();
    for (int s = 0; s < 16; s++) {
        const int b = s & 1;
        if (s + 1 < 16) load_chunk(s + 1, b ^ 1);
        CP_COMMIT();
        CP_WAIT(1);
        __syncthreads();
        const u32 abase = sb + b * P1_BUF;
        const u32 bbase = abase + 2 * P1_TILE;
#pragma unroll
        for (int ks = 0; ks < 4; ks++) {
            const int k16 = ks * 16;
            const u32 acol = (u32)(k16 + ((lane >> 4) << 3));
            const u32 arow = (u32)(m_base + (lane & 15));
            const u32 brow = (u32)(n_base + (lane & 7) + ((lane & 16) >> 1));
            const u32 bcol = (u32)(k16 + (lane & 8));
            u32 af[4][4], bh[8], bl[8];
#pragma unroll
            for (int j = 0; j < 2; j++) {
                u32 bd = bbase + ((brow + j*16) * P1_AST + bcol) * 2;
                ldmx4(&bh[j*4], bd);
                ldmx4(&bl[j*4], bd + P1_TILE);
            }
#pragma unroll
            for (int im = 0; im < 4; im++)
                ldmx4(af[im], abase + ((arow + im*16) * P1_AST + acol) * 2);   // Ah
#pragma unroll
            for (int im = 0; im < 4; im++)
#pragma unroll
                for (int jn = 0; jn < 4; jn++) {
                    mma16816(acc[im][jn], af[im], &bh[jn*2]);   // Ah*Bh
                    mma16816(acc[im][jn], af[im], &bl[jn*2]);   // Ah*Bl
                }
#pragma unroll
            for (int im = 0; im < 4; im++)
                ldmx4(af[im], abase + P1_TILE + ((arow + im*16) * P1_AST + acol) * 2);  // Al
#pragma unroll
            for (int im = 0; im < 4; im++)
#pragma unroll
                for (int jn = 0; jn < 4; jn++)
                    mma16816(acc[im][jn], af[im], &bh[jn*2]);   // Al*Bh
        }
        __syncthreads();
    }

    // epilogue: add biases, store fp32
#pragma unroll
    for (int im = 0; im < 4; im++) {
        int r0 = bm + m_base + im*16 + (lane >> 2);
#pragma unroll
        for (int jn = 0; jn < 4; jn++) {
            int n = bn + n_base + jn*8 + (lane & 3) * 2;
            float2 b1 = *(const float2*)(bih + n);
            float2 b2 = *(const float2*)(bhh + n);
            float bx = b1.x + b2.x, by = b1.y + b2.y;
            float2 v0 = make_float2(acc[im][jn][0] + bx, acc[im][jn][1] + by);
            float2 v1 = make_float2(acc[im][jn][2] + bx, acc[im][jn][3] + by);
            *(float2*)(out + (size_t)r0 * HH + n)       = v0;
            *(float2*)(out + (size_t)(r0+8) * HH + n)   = v1;
        }
    }
}

// ============================================================================
// Phase 2: recurrence. 128 persistent blocks (4 mt x 64 rows, 32 nt x 32 cols),
// Whh slice persistent in SMEM, A pipelined with KC=128 (8 steps), 128 groups.
// KEY: 3 separate accumulator sets (one per split product) -> 12 independent
// MMA chains per warp, hiding HMMA latency at 1 warp/SMSP.
// ============================================================================
#define P2_AST 136
#define P2_ATILE (64*P2_AST*2)     // 17408
#define P2_ABUF  (2*P2_ATILE)      // 34816
#define P2_BST 1032
#define P2_BTILE (32*P2_BST*2)     // 66048
#define P2_BYTES (2*P2_BTILE + 2*P2_ABUF)   // 201728

__global__ __launch_bounds__(128, 1)
void rnn2_kernel(float* __restrict__ out)
{
    extern __shared__ char smem[];
    const u32 sb  = smem_u32(smem);
    const u32 sbB = sb;                     // Bh, Bl at +P2_BTILE
    const u32 sbA = sb + 2 * P2_BTILE;
    const int tid = threadIdx.x, wid = tid >> 5, lane = tid & 31;
    const int mt  = blockIdx.x >> 5;        // 0..3  -> rows mt*64
    const int ntc = blockIdx.x & 31;        // 0..31 -> cols ntc*32
    const int wm = wid >> 1, wn = wid & 1;  // warp tile 32m x 16n
    const u32 NB = 128;

    // ---- persistent Whh slice (32 n-rows x 1024 k), hi+lo ----
#pragma unroll
    for (int it = 0; it < 32; it++) {
        int v = tid + it * 128;             // 0..4095
        int r = v >> 7, c = (v & 127) * 8;
        u32 so = (u32)(r * P2_BST + c) * 2;
        size_t gw = (size_t)(ntc*32 + r) * HH + c;
        CP16(sbB + so,            g_Whhh + gw);
        CP16(sbB + P2_BTILE + so, g_Whhl + gw);
    }
    CP_COMMIT(); CP_WAIT(0);
    __syncthreads();

    for (int g = 0; g < 128; g++) {
        const int rslot = g & 1, wslot = rslot ^ 1;
        const __nv_bfloat16* Ah = g_rh + (size_t)rslot * RING;
        const __nv_bfloat16* Al = g_rl + (size_t)rslot * RING;

        auto load_a = [&](int s, int buf) {
            const int k0 = s * 128;
            const u32 base = sbA + buf * P2_ABUF;
#pragma unroll
            for (int it = 0; it < 8; it++) {
                int v = tid + it * 128;     // 0..1023
                int r = v >> 4, c = (v & 15) * 8;
                u32 so = (u32)(r * P2_AST + c) * 2;
                size_t ga = (size_t)(mt*64 + r) * HH + k0 + c;
                CP16(base + so,             Ah + ga);
                CP16(base + P2_ATILE + so,  Al + ga);
            }
        };

        float a0[2][2][4], a1[2][2][4], a2[2][2][4];
#pragma unroll
        for (int i = 0; i < 2; i++)
#pragma unroll
            for (int j = 0; j < 2; j++)
#pragma unroll
                for (int q = 0; q < 4; q++) {
                    a0[i][j][q] = 0.0f; a1[i][j][q] = 0.0f; a2[i][j][q] = 0.0f;
                }

        load_a(0, 0); CP_COMMIT();
        for (int s = 0; s < 8; s++) {
            const int b = s & 1;
            if (s + 1 < 8) load_a(s + 1, b ^ 1);
            CP_COMMIT();
            CP_WAIT(1);
            __syncthreads();
            const u32 abase = sbA + b * P2_ABUF;
#pragma unroll
            for (int ks = 0; ks < 8; ks++) {
                const int k16a = ks * 16;
                const int k16g = s * 128 + k16a;
                const u32 arow = (u32)(wm*32 + (lane & 15));
                const u32 acol = (u32)(k16a + ((lane >> 4) << 3));
                const u32 brow = (u32)(wn*16 + (lane & 7) + ((lane & 16) >> 1));
                const u32 bcol = (u32)(k16g + (lane & 8));
                u32 ah[2][4], al[2][4], bh[4], bl[4];
                u32 bd = sbB + (brow * P2_BST + bcol) * 2;
                ldmx4(bh, bd);
                ldmx4(bl, bd + P2_BTILE);
#pragma unroll
                for (int im = 0; im < 2; im++) {
                    u32 ad = abase + ((arow + im*16) * P2_AST + acol) * 2;
                    ldmx4(ah[im], ad);
                    ldmx4(al[im], ad + P2_ATILE);
                }
                // 12 independent accumulator chains per k-step
#pragma unroll
                for (int im = 0; im < 2; im++)
#pragma unroll
                    for (int jn = 0; jn < 2; jn++) {
                        mma16816(a0[im][jn], ah[im], &bh[jn*2]);
                        mma16816(a1[im][jn], ah[im], &bl[jn*2]);
                        mma16816(a2[im][jn], al[im], &bh[jn*2]);
                    }
            }
            __syncthreads();
        }

        // ---- epilogue: tanh(pre + sum) -> out (fp32) + hidden ring (bf16 hi/lo)
#pragma unroll
        for (int im = 0; im < 2; im++) {
            int rA = mt*64 + wm*32 + im*16 + (lane >> 2);
#pragma unroll
            for (int jn = 0; jn < 2; jn++) {
                int n = ntc*32 + wn*16 + jn*8 + (lane & 3) * 2;
#pragma unroll
                for (int half = 0; half < 2; half++) {
                    int r = rA + half * 8;
                    float v0 = a0[im][jn][half*2]   + a1[im][jn][half*2]   + a2[im][jn][half*2];
                    float v1 = a0[im][jn][half*2+1] + a1[im][jn][half*2+1] + a2[im][jn][half*2+1];
                    int d = r >> 6, bidx = r & 63, t = 4*g + d;
                    float* prow = out + ((size_t)bidx * SSL + t) * HH + n;
                    float2 p = *(float2*)prow;
                    float h0 = fast_tanh(p.x + v0);
                    float h1 = fast_tanh(p.y + v1);
                    *(float2*)prow = make_float2(h0, h1);
                    float q0 = bf16_hi_f32(h0), q1 = bf16_hi_f32(h1);
                    size_t rb = (size_t)wslot * RING + (size_t)r * HH + n;
                    *(u32*)(g_rh + rb) = pack_bf16x2(h0, h1);
                    *(u32*)(g_rl + rb) = pack_bf16x2(h0 - q0, h1 - q1);
                }
            }
        }

        // ---- grid barrier ----
        if (g + 1 < 128) {
            __threadfence();
            __syncthreads();
            if (tid == 0) {
                u32 v = atomicAdd(&g_bars[g], 1u) + 1u;
                u32 target = ((v + NB - 1u) / NB) * NB;
                while (*(volatile u32*)&g_bars[g] < target) { }
            }
            __syncthreads();
        }
    }
}

// ============================================================================
// Phase 3: h_final[d,b,h] = outs[b, S-4+d, h]
// ============================================================================
__global__ void copy_final_kernel(float* __restrict__ out)
{
    int idx = blockIdx.x * blockDim.x + threadIdx.x;
    const int total = 4 * BB * HH;
    if (idx < total) {
        int h  = idx & (HH - 1);
        int b  = (idx >> 10) & (BB - 1);
        int dd = idx >> 16;
        out[(size_t)BB*SSL*HH + idx] =
            out[(size_t)(b*SSL + (SSL - 4 + dd)) * HH + h];
    }
}

extern "C" void kernel_launch(void* const* d_in, const int* in_sizes, int n_in,
                              void* d_out, int out_size)
{
    const float* inputs = (const float*)d_in[0];
    const float* hidden = (const float*)d_in[1];
    const float* Wih    = (const float*)d_in[2];
    const float* Whh    = (const float*)d_in[3];
    const float* bih    = (const float*)d_in[4];
    const float* bhh    = (const float*)d_in[5];
    float* out = (float*)d_out;

    cudaFuncSetAttribute(gemm1_kernel, cudaFuncAttributeMaxDynamicSharedMemorySize, P1_BYTES);
    cudaFuncSetAttribute(rnn2_kernel,  cudaFuncAttributeMaxDynamicSharedMemorySize, P2_BYTES);

    split_kernel<<<(BB*SSL*II/4 + 255)/256, 256>>>(inputs, 0, BB*SSL*II/4);
    split_kernel<<<(II*HH/4 + 255)/256, 256>>>(Wih, 1, II*HH/4);
    split_kernel<<<(HH*HH/4 + 255)/256, 256>>>(Whh, 2, HH*HH/4);
    split_kernel<<<(4*BB*HH/4 + 255)/256, 256>>>(hidden, 3, 4*BB*HH/4);

    dim3 g1(HH/128, (BB*SSL)/128);     // (8, 256) = 2048 blocks
    gemm1_kernel<<<g1, 256, P1_BYTES>>>(bih, bhh, out);

    rnn2_kernel<<<128, 128, P2_BYTES>>>(out);

    copy_final_kernel<<<(4*BB*HH + 255)/256, 256>>>(out);
}